// round 11
// baseline (speedup 1.0000x reference)
#include <cuda_runtime.h>

// Problem constants (fixed by the reference)
#define BB   256
#define TT   16384
#define WIN  5
#define HID  5
#define NN   (TT - WIN)   // 16379

// ---- Fused kernel config ----
#define TPB    1024                         // 32 warps
#define NPB    120                          // n per block
#define NBLK   ((NN + NPB - 1) / NPB)       // 137 blocks (single wave on 148 SMs)
#define ROWB   136                          // stat row length (padded)
#define NWARP  32
#define RPW    (BB / NWARP)                 // 8 rows per warp
#define NPOOL  8                            // pool slots (multi-round reduce)
#define NSTAT  7                            // C_0..C_5, mean
#define STATF  (NSTAT * ROWB)               // 952 floats

__device__ __forceinline__ int triidx(int i, int j) {
    return 7 * i - (i * (i - 1)) / 2 + (j - i);   // upper-tri 7x7, i <= j
}

__global__ void __launch_bounds__(TPB, 1)
llsa_fused_kernel(const float* __restrict__ series,
                  const float* __restrict__ weight,
                  const float* __restrict__ bias,
                  const float* __restrict__ thr_p,
                  float* __restrict__ out)
{
    __shared__ float pool[NPOOL * STATF];    // 30.5 KB
    __shared__ float R[NSTAT][ROWB + 4];     // reduced stats
    __shared__ float sM[28];
    __shared__ float sloss[NPB + 2];

    const int tid  = threadIdx.x;
    const int slot = tid & 31;        // t4-slot: t-local = slot*4 .. +3
    const int rg   = tid >> 5;        // warp id 0..31 -> rows rg*8 .. rg*8+7
    const int n0   = blockIdx.x * NPB;
    const int tl   = slot * 4;

    float acc[NSTAT][4];
#pragma unroll
    for (int s = 0; s < NSTAT; s++)
#pragma unroll
        for (int i = 0; i < 4; i++) acc[s][i] = 0.0f;

    // ---- Main loop: direct gmem, no smem, no syncs. ----
    const float* base = series + (size_t)(rg * RPW) * TT + (n0 + tl);
    const bool fast = (n0 + tl + 12 <= TT);

    if (fast) {
#pragma unroll
        for (int r = 0; r < RPW; r++) {
            const float* rp = base + (size_t)r * TT;
            const float4 a0 = *reinterpret_cast<const float4*>(rp);
            const float4 a1 = *reinterpret_cast<const float4*>(rp + 4);
            const float4 a2 = *reinterpret_cast<const float4*>(rp + 8);
            const float x[9] = {a0.x, a0.y, a0.z, a0.w,
                                a1.x, a1.y, a1.z, a1.w, a2.x};
#pragma unroll
            for (int i = 0; i < 4; i++) {
                acc[6][i] += x[i];
#pragma unroll
                for (int d = 0; d < 6; d++)
                    acc[d][i] = fmaf(x[i], x[i + d], acc[d][i]);
            }
        }
    } else {
        // Last block's high slots only: scalar guarded loads.
        for (int r = 0; r < RPW; r++) {
            const float* rp = base + (size_t)r * TT;
            float x[12];
#pragma unroll
            for (int j = 0; j < 12; j++)
                x[j] = (n0 + tl + j < TT) ? rp[j] : 0.0f;
#pragma unroll
            for (int i = 0; i < 4; i++) {
                acc[6][i] += x[i];
#pragma unroll
                for (int d = 0; d < 6; d++)
                    acc[d][i] = fmaf(x[i], x[i + d], acc[d][i]);
            }
        }
    }

    // ---- Multi-round cross-warp reduction (32 warps -> 8 pool slots) ----
    const int grp = rg >> 3;          // 0..3
    const int ps  = rg & 7;           // pool slot

    if (grp == 0) {
#pragma unroll
        for (int s = 0; s < NSTAT; s++)
#pragma unroll
            for (int i = 0; i < 4; i++)
                pool[ps * STATF + s * ROWB + tl + i] = acc[s][i];
    }
    __syncthreads();
#pragma unroll
    for (int g2 = 1; g2 < 4; g2++) {
        if (grp == g2) {
#pragma unroll
            for (int s = 0; s < NSTAT; s++)
#pragma unroll
                for (int i = 0; i < 4; i++)
                    pool[ps * STATF + s * ROWB + tl + i] += acc[s][i];
        }
        __syncthreads();
    }

    for (int e = tid; e < NSTAT * 128; e += TPB) {   // only k<128 is consumed
        const int s = e >> 7;
        const int k = e & 127;
        float v = 0.0f;
#pragma unroll
        for (int w = 0; w < NPOOL; w++)
            v += pool[w * STATF + s * ROWB + k];
        R[s][k] = v;
    }

    // ---- Build folded M: r_h = (W[h,0..4], 0, b_h), r_h[1+h] -= 1 ----
    if (tid < 28) {
        int i = 0, j = tid;
        while (j >= 7 - i) { j -= 7 - i; i++; }
        j += i;
        float m = 0.0f;
#pragma unroll
        for (int h = 0; h < HID; h++) {
            float ri = (i < WIN) ? __ldg(&weight[h * WIN + i]) : 0.0f;
            float rj = (j < WIN) ? __ldg(&weight[h * WIN + j]) : 0.0f;
            if (i == 1 + h) ri -= 1.0f;
            if (j == 1 + h) rj -= 1.0f;
            if (i == 6) ri = __ldg(&bias[h]);
            if (j == 6) rj = __ldg(&bias[h]);
            m = fmaf(ri, rj, m);
        }
        sM[tid] = (i == j) ? m : 2.0f * m;
    }
    __syncthreads();

    // ---- loss[n0+k] = (1/(B*H)) * sum_{i<=j} Mfold_ij * Z_ij ----
    auto compute_loss = [&](int k) -> float {
        float s = sM[triidx(6, 6)] * (float)BB;
#pragma unroll
        for (int i = 0; i < 6; i++)
            s = fmaf(sM[triidx(i, 6)], R[6][k + i], s);   // mean terms
#pragma unroll
        for (int i = 0; i < 6; i++)
            s = fmaf(sM[triidx(i, i)], R[0][k + i], s);   // diagonal (lag 0)
#pragma unroll
        for (int i = 0; i < 6; i++)
#pragma unroll
            for (int j = i + 1; j < 6; j++)
                s = fmaf(sM[triidx(i, j)], R[j - i][k + i], s);
        return s * (1.0f / (float)(BB * HID));
    };

    // NPB losses + one neighbor (k = NPB) for the cross-block diff.
    float L = 0.0f;
    const int n = n0 + tid;
    if (tid <= NPB && n < NN) L = compute_loss(tid);
    if (tid <= NPB) sloss[tid] = L;
    __syncthreads();

    if (tid < NPB && n < NN) {
        out[n] = L;
        if (n < NN - 1) {
            const float d = fabsf(sloss[tid + 1] - L);
            out[NN + n] = d;
            out[2 * NN - 1 + n] = (d > __ldg(thr_p)) ? 1.0f : 0.0f;
        }
    }
}

extern "C" void kernel_launch(void* const* d_in, const int* in_sizes, int n_in,
                              void* d_out, int out_size)
{
    const float* series = (const float*)d_in[0];
    const float* weight = (const float*)d_in[1];
    const float* bias   = (const float*)d_in[2];
    const float* thr    = (const float*)d_in[3];
    float* out = (float*)d_out;

    llsa_fused_kernel<<<NBLK, TPB>>>(series, weight, bias, thr, out);
}

// round 12
// speedup vs baseline: 1.4289x; 1.4289x over previous
#include <cuda_runtime.h>

// Problem constants (fixed by the reference)
#define BB   256
#define TT   16384
#define WIN  5
#define HID  5
#define NN   (TT - WIN)   // 16379

// ---- Fused kernel config ----
#define TPB    512                          // 16 warps; 2 CTAs resident per SM
#define NPB    56                           // n per block
#define NBLK   ((NN + NPB - 1) / NPB)       // 293 blocks (~2 CTAs x 148 SMs)
#define NWARP  16
#define RPW    (BB / NWARP)                 // 16 rows per warp
#define TPT    2                            // t per thread (slot covers 2 stats)
#define TCOV   64                           // stat positions per warp (32*2)
#define ROWB   68                           // stat row stride (64 + pad)
#define NPOOL  8                            // pool slots (two-stage reduce)
#define NSTAT  7                            // C_0..C_5, mean
#define STATF  (NSTAT * ROWB)               // 476 floats

__device__ __forceinline__ int triidx(int i, int j) {
    return 7 * i - (i * (i - 1)) / 2 + (j - i);   // upper-tri 7x7, i <= j
}

__global__ void __launch_bounds__(TPB, 2)
llsa_fused_kernel(const float* __restrict__ series,
                  const float* __restrict__ weight,
                  const float* __restrict__ bias,
                  const float* __restrict__ thr_p,
                  float* __restrict__ out)
{
    __shared__ float pool[NPOOL * STATF];    // 15.2 KB
    __shared__ float R[NSTAT][ROWB];         // reduced stats
    __shared__ float sM[28];
    __shared__ float sloss[NPB + 2];

    const int tid  = threadIdx.x;
    const int slot = tid & 31;        // slot covers stats k = slot*2, slot*2+1
    const int rg   = tid >> 5;        // warp id 0..15 -> rows rg*16 .. rg*16+15
    const int n0   = blockIdx.x * NPB;
    const int tl   = slot * TPT;

    float acc[NSTAT][TPT];
#pragma unroll
    for (int s = 0; s < NSTAT; s++)
#pragma unroll
        for (int i = 0; i < TPT; i++) acc[s][i] = 0.0f;

    // ---- Main loop: direct gmem, no smem, no syncs. ----
    // Thread needs x[t .. t+7] for t = n0 + tl (4 x float2, 8B-aligned).
    const float* base = series + (size_t)(rg * RPW) * TT + (n0 + tl);
    const bool fast = (n0 + tl + 8 <= TT);

    if (fast) {
#pragma unroll 4
        for (int r = 0; r < RPW; r++) {
            const float* rp = base + (size_t)r * TT;
            const float2 a0 = *reinterpret_cast<const float2*>(rp);
            const float2 a1 = *reinterpret_cast<const float2*>(rp + 2);
            const float2 a2 = *reinterpret_cast<const float2*>(rp + 4);
            const float2 a3 = *reinterpret_cast<const float2*>(rp + 6);
            const float x[8] = {a0.x, a0.y, a1.x, a1.y,
                                a2.x, a2.y, a3.x, a3.y};
#pragma unroll
            for (int i = 0; i < TPT; i++) {
                acc[6][i] += x[i];
#pragma unroll
                for (int d = 0; d < 6; d++)
                    acc[d][i] = fmaf(x[i], x[i + d], acc[d][i]);
            }
        }
    } else {
        // Last blocks' high slots only: scalar guarded loads.
        for (int r = 0; r < RPW; r++) {
            const float* rp = base + (size_t)r * TT;
            float x[8];
#pragma unroll
            for (int j = 0; j < 8; j++)
                x[j] = (n0 + tl + j < TT) ? rp[j] : 0.0f;
#pragma unroll
            for (int i = 0; i < TPT; i++) {
                acc[6][i] += x[i];
#pragma unroll
                for (int d = 0; d < 6; d++)
                    acc[d][i] = fmaf(x[i], x[i + d], acc[d][i]);
            }
        }
    }

    // ---- Two-stage cross-warp reduction (16 warps -> 8 pool slots -> R) ----
    if (rg >= NPOOL) {
#pragma unroll
        for (int s = 0; s < NSTAT; s++)
#pragma unroll
            for (int i = 0; i < TPT; i++)
                pool[(rg - NPOOL) * STATF + s * ROWB + tl + i] = acc[s][i];
    }
    __syncthreads();
    if (rg < NPOOL) {
#pragma unroll
        for (int s = 0; s < NSTAT; s++)
#pragma unroll
            for (int i = 0; i < TPT; i++)
                pool[rg * STATF + s * ROWB + tl + i] += acc[s][i];
    }
    __syncthreads();

    for (int e = tid; e < NSTAT * TCOV; e += TPB) {   // k < 64 (need k <= 61)
        const int s = e >> 6;
        const int k = e & 63;
        float v = 0.0f;
#pragma unroll
        for (int w = 0; w < NPOOL; w++)
            v += pool[w * STATF + s * ROWB + k];
        R[s][k] = v;
    }

    // ---- Build folded M: r_h = (W[h,0..4], 0, b_h), r_h[1+h] -= 1 ----
    if (tid < 28) {
        int i = 0, j = tid;
        while (j >= 7 - i) { j -= 7 - i; i++; }
        j += i;
        float m = 0.0f;
#pragma unroll
        for (int h = 0; h < HID; h++) {
            float ri = (i < WIN) ? __ldg(&weight[h * WIN + i]) : 0.0f;
            float rj = (j < WIN) ? __ldg(&weight[h * WIN + j]) : 0.0f;
            if (i == 1 + h) ri -= 1.0f;
            if (j == 1 + h) rj -= 1.0f;
            if (i == 6) ri = __ldg(&bias[h]);
            if (j == 6) rj = __ldg(&bias[h]);
            m = fmaf(ri, rj, m);
        }
        sM[tid] = (i == j) ? m : 2.0f * m;
    }
    __syncthreads();

    // ---- loss[n0+k] = (1/(B*H)) * sum_{i<=j} Mfold_ij * Z_ij ----
    auto compute_loss = [&](int k) -> float {
        float s = sM[triidx(6, 6)] * (float)BB;
#pragma unroll
        for (int i = 0; i < 6; i++)
            s = fmaf(sM[triidx(i, 6)], R[6][k + i], s);   // mean terms
#pragma unroll
        for (int i = 0; i < 6; i++)
            s = fmaf(sM[triidx(i, i)], R[0][k + i], s);   // diagonal (lag 0)
#pragma unroll
        for (int i = 0; i < 6; i++)
#pragma unroll
            for (int j = i + 1; j < 6; j++)
                s = fmaf(sM[triidx(i, j)], R[j - i][k + i], s);
        return s * (1.0f / (float)(BB * HID));
    };

    // NPB losses + one neighbor (k = NPB) for the cross-block diff.
    float L = 0.0f;
    const int n = n0 + tid;
    if (tid <= NPB && n < NN) L = compute_loss(tid);
    if (tid <= NPB) sloss[tid] = L;
    __syncthreads();

    if (tid < NPB && n < NN) {
        out[n] = L;
        if (n < NN - 1) {
            const float d = fabsf(sloss[tid + 1] - L);
            out[NN + n] = d;
            out[2 * NN - 1 + n] = (d > __ldg(thr_p)) ? 1.0f : 0.0f;
        }
    }
}

extern "C" void kernel_launch(void* const* d_in, const int* in_sizes, int n_in,
                              void* d_out, int out_size)
{
    const float* series = (const float*)d_in[0];
    const float* weight = (const float*)d_in[1];
    const float* bias   = (const float*)d_in[2];
    const float* thr    = (const float*)d_in[3];
    float* out = (float*)d_out;

    llsa_fused_kernel<<<NBLK, TPB>>>(series, weight, bias, thr, out);
}

// round 14
// speedup vs baseline: 1.7701x; 1.2388x over previous
#include <cuda_runtime.h>
#include <cstdint>

// Problem constants (fixed by the reference)
#define BB   256
#define TT   16384
#define WIN  5
#define HID  5
#define NN   (TT - WIN)   // 16379

// ---- Fused kernel config ----
#define TPB    512                          // 16 warps; 2 CTAs resident per SM
#define NPB    56                           // n per block (multiple of 4!)
#define NBLK   ((NN + NPB - 1) / NPB)       // 293 blocks
#define NWARP  16
#define RPW    (BB / NWARP)                 // 16 rows per warp
#define TPT    2                            // stats per thread
#define TCOV   64                           // stat positions per warp
#define ROWB   68                           // stat row stride (64 + pad)
#define NPOOL  8
#define NSTAT  7                            // C_0..C_5, mean
#define STATF  (NSTAT * ROWB)               // 476 floats

// ---- cp.async pipeline ----
#define DEPTH   4                           // rows in flight per warp
#define CHUNKS  18                          // 16B chunks per row (72 floats >= 70 needed)
#define ROWBUF  80                          // floats per row buffer (stride)

__device__ __forceinline__ void cp16(void* dst_smem, const void* src) {
    uint32_t d = (uint32_t)__cvta_generic_to_shared(dst_smem);
    asm volatile("cp.async.cg.shared.global [%0], [%1], 16;\n" :: "r"(d), "l"(src));
}
__device__ __forceinline__ void cp_commit() {
    asm volatile("cp.async.commit_group;\n" ::: "memory");
}
__device__ __forceinline__ void cp_wait() {
    asm volatile("cp.async.wait_group %0;\n" :: "n"(DEPTH - 1) : "memory");
}

__device__ __forceinline__ int triidx(int i, int j) {
    return 7 * i - (i * (i - 1)) / 2 + (j - i);   // upper-tri 7x7, i <= j
}

__global__ void __launch_bounds__(TPB, 2)
llsa_fused_kernel(const float* __restrict__ series,
                  const float* __restrict__ weight,
                  const float* __restrict__ bias,
                  const float* __restrict__ thr_p,
                  float* __restrict__ out)
{
    __shared__ float stage[NWARP][DEPTH][ROWBUF];   // 20 KB
    __shared__ float pool[NPOOL * STATF];           // 15.2 KB
    __shared__ float R[NSTAT][ROWB];
    __shared__ float sM[28];
    __shared__ float sloss[NPB + 2];

    const int tid  = threadIdx.x;
    const int slot = tid & 31;        // stats k = slot*2, slot*2+1
    const int rg   = tid >> 5;        // warp id -> rows rg*16 .. rg*16+15
    const int n0   = blockIdx.x * NPB;   // multiple of 4 -> 16B-aligned chunks
    const int tl   = slot * TPT;

    // Stage source address for this lane (fixed chunk column, row varies).
    // Clamp keeps the 16B chunk in-bounds for the last block; clamped values
    // are never consumed (only stats k <= NPB+5 are read downstream).
    int tcol = n0 + 4 * slot;                 // chunk start (lane < CHUNKS)
    if (tcol + 4 > TT) tcol = TT - 4;
    const float* srccol = series + (size_t)(rg * RPW) * TT + tcol;
    const bool loader = (slot < CHUNKS);

    // ---- Pipeline prologue: prefetch rows 0..DEPTH-1 ----
#pragma unroll
    for (int r = 0; r < DEPTH; r++) {
        if (loader)
            cp16(&stage[rg][r][4 * slot], srccol + (size_t)r * TT);
        cp_commit();
    }

    float acc[NSTAT][TPT];
#pragma unroll
    for (int s = 0; s < NSTAT; s++)
#pragma unroll
        for (int i = 0; i < TPT; i++) acc[s][i] = 0.0f;

    // ---- Main loop: per-warp async pipeline, no block barriers ----
#pragma unroll
    for (int r = 0; r < RPW; r++) {
        cp_wait();                 // row r landed (<= DEPTH-1 groups pending)
        __syncwarp();

        const float2* wb = reinterpret_cast<const float2*>(
                               &stage[rg][r & (DEPTH - 1)][0]) + slot;
        const float2 a0 = wb[0];
        const float2 a1 = wb[1];
        const float2 a2 = wb[2];
        const float2 a3 = wb[3];
        const float x[8] = {a0.x, a0.y, a1.x, a1.y, a2.x, a2.y, a3.x, a3.y};

#pragma unroll
        for (int i = 0; i < TPT; i++) {
            acc[6][i] += x[i];
#pragma unroll
            for (int d = 0; d < 6; d++)
                acc[d][i] = fmaf(x[i], x[i + d], acc[d][i]);
        }

        __syncwarp();              // all lanes done reading slot r&3
        if (r + DEPTH < RPW && loader)
            cp16(&stage[rg][(r + DEPTH) & (DEPTH - 1)][4 * slot],
                 srccol + (size_t)(r + DEPTH) * TT);
        cp_commit();               // keep per-thread group count uniform
    }

    // ---- Two-stage cross-warp reduction (16 warps -> 8 pool slots -> R) ----
    if (rg >= NPOOL) {
#pragma unroll
        for (int s = 0; s < NSTAT; s++)
#pragma unroll
            for (int i = 0; i < TPT; i++)
                pool[(rg - NPOOL) * STATF + s * ROWB + tl + i] = acc[s][i];
    }
    __syncthreads();
    if (rg < NPOOL) {
#pragma unroll
        for (int s = 0; s < NSTAT; s++)
#pragma unroll
            for (int i = 0; i < TPT; i++)
                pool[rg * STATF + s * ROWB + tl + i] += acc[s][i];
    }
    __syncthreads();

    for (int e = tid; e < NSTAT * TCOV; e += TPB) {   // k < 64 (need <= 61)
        const int s = e >> 6;
        const int k = e & 63;
        float v = 0.0f;
#pragma unroll
        for (int w = 0; w < NPOOL; w++)
            v += pool[w * STATF + s * ROWB + k];
        R[s][k] = v;
    }

    // ---- Build folded M: r_h = (W[h,0..4], 0, b_h), r_h[1+h] -= 1 ----
    if (tid < 28) {
        int i = 0, j = tid;
        while (j >= 7 - i) { j -= 7 - i; i++; }
        j += i;
        float m = 0.0f;
#pragma unroll
        for (int h = 0; h < HID; h++) {
            float ri = (i < WIN) ? __ldg(&weight[h * WIN + i]) : 0.0f;
            float rj = (j < WIN) ? __ldg(&weight[h * WIN + j]) : 0.0f;
            if (i == 1 + h) ri -= 1.0f;
            if (j == 1 + h) rj -= 1.0f;
            if (i == 6) ri = __ldg(&bias[h]);
            if (j == 6) rj = __ldg(&bias[h]);
            m = fmaf(ri, rj, m);
        }
        sM[tid] = (i == j) ? m : 2.0f * m;
    }
    __syncthreads();

    // ---- loss[n0+k] = (1/(B*H)) * sum_{i<=j} Mfold_ij * Z_ij ----
    auto compute_loss = [&](int k) -> float {
        float s = sM[triidx(6, 6)] * (float)BB;
#pragma unroll
        for (int i = 0; i < 6; i++)
            s = fmaf(sM[triidx(i, 6)], R[6][k + i], s);   // mean terms
#pragma unroll
        for (int i = 0; i < 6; i++)
            s = fmaf(sM[triidx(i, i)], R[0][k + i], s);   // diagonal (lag 0)
#pragma unroll
        for (int i = 0; i < 6; i++)
#pragma unroll
            for (int j = i + 1; j < 6; j++)
                s = fmaf(sM[triidx(i, j)], R[j - i][k + i], s);
        return s * (1.0f / (float)(BB * HID));
    };

    // NPB losses + one neighbor (k = NPB) for the cross-block diff.
    float L = 0.0f;
    const int n = n0 + tid;
    if (tid <= NPB && n < NN) L = compute_loss(tid);
    if (tid <= NPB) sloss[tid] = L;
    __syncthreads();

    if (tid < NPB && n < NN) {
        out[n] = L;
        if (n < NN - 1) {
            const float d = fabsf(sloss[tid + 1] - L);
            out[NN + n] = d;
            out[2 * NN - 1 + n] = (d > __ldg(thr_p)) ? 1.0f : 0.0f;
        }
    }
}

extern "C" void kernel_launch(void* const* d_in, const int* in_sizes, int n_in,
                              void* d_out, int out_size)
{
    const float* series = (const float*)d_in[0];
    const float* weight = (const float*)d_in[1];
    const float* bias   = (const float*)d_in[2];
    const float* thr    = (const float*)d_in[3];
    float* out = (float*)d_out;

    llsa_fused_kernel<<<NBLK, TPB>>>(series, weight, bias, thr, out);
}

// round 16
// speedup vs baseline: 2.1801x; 1.2316x over previous
#include <cuda_runtime.h>

// Problem constants (fixed by the reference)
#define BB   256
#define TT   16384
#define WIN  5
#define HID  5
#define NN   (TT - WIN)   // 16379

// ---- Fused kernel config ----
#define TPB    512                          // 16 warps, 1 CTA/SM (128-reg budget)
#define NWARP  16
#define RPW    16                           // rows per warp (16*16 = 256 = BB)
#define NPB    120                          // n per block
#define NBLK   ((NN + NPB - 1) / NPB)       // 137 blocks (one wave)
#define TCOV   128                          // stat positions covered per warp
#define ROWB   132                          // stat row stride (128 + 4 pad, 16B-aligned)
#define NPOOL  8
#define NSTAT  7                            // C_0..C_5, mean
#define STATF  (NSTAT * ROWB)               // 924 floats
#define PF     4                            // register prefetch depth (rows)

__device__ __forceinline__ int triidx(int i, int j) {
    return 7 * i - (i * (i - 1)) / 2 + (j - i);   // upper-tri 7x7, i <= j
}

__global__ void __launch_bounds__(TPB, 1)
llsa_fused_kernel(const float* __restrict__ series,
                  const float* __restrict__ weight,
                  const float* __restrict__ bias,
                  const float* __restrict__ thr_p,
                  float* __restrict__ out)
{
    __shared__ float pool[NPOOL * STATF];    // 29.6 KB
    __shared__ float R[NSTAT][ROWB];
    __shared__ float sM[28];
    __shared__ float sloss[NPB + 2];

    const int tid  = threadIdx.x;
    const int slot = tid & 31;        // lane: owns stats k = slot*4 .. +3
    const int rg   = tid >> 5;        // warp id -> rows rg*16 .. rg*16+15
    const int n0   = blockIdx.x * NPB;
    const int tl   = slot * 4;

    // Disjoint per-lane float4 column; clamp keeps last block in-bounds
    // (clamped lanes' stats are never consumed downstream).
    int tcol = n0 + tl;
    if (tcol > TT - 4) tcol = TT - 4;
    const float* src = series + (size_t)(rg * RPW) * TT + tcol;

    // ---- Register prefetch pipeline ----
    float4 buf[PF];
#pragma unroll
    for (int r = 0; r < PF; r++)
        buf[r] = __ldg(reinterpret_cast<const float4*>(src + (size_t)r * TT));

    float acc[NSTAT][4];
#pragma unroll
    for (int s = 0; s < NSTAT; s++)
#pragma unroll
        for (int i = 0; i < 4; i++) acc[s][i] = 0.0f;

#pragma unroll
    for (int r = 0; r < RPW; r++) {
        const float4 v0 = buf[r & (PF - 1)];
        if (r + PF < RPW)
            buf[r & (PF - 1)] = __ldg(reinterpret_cast<const float4*>(
                                          src + (size_t)(r + PF) * TT));

        // Halo from neighbor lanes (edge-lane garbage is never consumed).
        const float x4 = __shfl_down_sync(0xffffffffu, v0.x, 1);
        const float x5 = __shfl_down_sync(0xffffffffu, v0.y, 1);
        const float x6 = __shfl_down_sync(0xffffffffu, v0.z, 1);
        const float x7 = __shfl_down_sync(0xffffffffu, v0.w, 1);
        const float x8 = __shfl_down_sync(0xffffffffu, v0.x, 2);
        const float x9 = __shfl_down_sync(0xffffffffu, v0.y, 2);
        const float x[10] = {v0.x, v0.y, v0.z, v0.w, x4, x5, x6, x7, x8, x9};

#pragma unroll
        for (int i = 0; i < 4; i++) {
            acc[6][i] += x[i];
#pragma unroll
            for (int d = 0; d < 6; d++)
                acc[d][i] = fmaf(x[i], x[i + d], acc[d][i]);
        }
    }

    // ---- Two-stage cross-warp reduction (16 warps -> 8 pool slots -> R) ----
    if (rg >= NPOOL) {
#pragma unroll
        for (int s = 0; s < NSTAT; s++) {
            float4 v = make_float4(acc[s][0], acc[s][1], acc[s][2], acc[s][3]);
            *reinterpret_cast<float4*>(
                &pool[(rg - NPOOL) * STATF + s * ROWB + tl]) = v;
        }
    }
    __syncthreads();
    if (rg < NPOOL) {
#pragma unroll
        for (int s = 0; s < NSTAT; s++) {
            float* p = &pool[rg * STATF + s * ROWB + tl];
            float4 v = *reinterpret_cast<const float4*>(p);
            v.x += acc[s][0]; v.y += acc[s][1];
            v.z += acc[s][2]; v.w += acc[s][3];
            *reinterpret_cast<float4*>(p) = v;
        }
    }
    __syncthreads();

    for (int e = tid; e < NSTAT * TCOV; e += TPB) {   // 896 entries, 2 iters
        const int s = e >> 7;
        const int k = e & 127;
        float v = 0.0f;
#pragma unroll
        for (int w = 0; w < NPOOL; w++)
            v += pool[w * STATF + s * ROWB + k];
        R[s][k] = v;
    }

    // ---- Build folded M: r_h = (W[h,0..4], 0, b_h), r_h[1+h] -= 1 ----
    if (tid < 28) {
        int i = 0, j = tid;
        while (j >= 7 - i) { j -= 7 - i; i++; }
        j += i;
        float m = 0.0f;
#pragma unroll
        for (int h = 0; h < HID; h++) {
            float ri = (i < WIN) ? __ldg(&weight[h * WIN + i]) : 0.0f;
            float rj = (j < WIN) ? __ldg(&weight[h * WIN + j]) : 0.0f;
            if (i == 1 + h) ri -= 1.0f;
            if (j == 1 + h) rj -= 1.0f;
            if (i == 6) ri = __ldg(&bias[h]);
            if (j == 6) rj = __ldg(&bias[h]);
            m = fmaf(ri, rj, m);
        }
        sM[tid] = (i == j) ? m : 2.0f * m;
    }
    __syncthreads();

    // ---- loss[n0+k] = (1/(B*H)) * sum_{i<=j} Mfold_ij * Z_ij ----
    auto compute_loss = [&](int k) -> float {
        float s = sM[triidx(6, 6)] * (float)BB;
#pragma unroll
        for (int i = 0; i < 6; i++)
            s = fmaf(sM[triidx(i, 6)], R[6][k + i], s);   // mean terms
#pragma unroll
        for (int i = 0; i < 6; i++)
            s = fmaf(sM[triidx(i, i)], R[0][k + i], s);   // diagonal (lag 0)
#pragma unroll
        for (int i = 0; i < 6; i++)
#pragma unroll
            for (int j = i + 1; j < 6; j++)
                s = fmaf(sM[triidx(i, j)], R[j - i][k + i], s);
        return s * (1.0f / (float)(BB * HID));
    };

    // NPB losses + one neighbor (k = NPB) for the cross-block diff.
    float L = 0.0f;
    const int n = n0 + tid;
    if (tid <= NPB && n < NN) L = compute_loss(tid);
    if (tid <= NPB) sloss[tid] = L;
    __syncthreads();

    if (tid < NPB && n < NN) {
        out[n] = L;
        if (n < NN - 1) {
            const float d = fabsf(sloss[tid + 1] - L);
            out[NN + n] = d;
            out[2 * NN - 1 + n] = (d > __ldg(thr_p)) ? 1.0f : 0.0f;
        }
    }
}

extern "C" void kernel_launch(void* const* d_in, const int* in_sizes, int n_in,
                              void* d_out, int out_size)
{
    const float* series = (const float*)d_in[0];
    const float* weight = (const float*)d_in[1];
    const float* bias   = (const float*)d_in[2];
    const float* thr    = (const float*)d_in[3];
    float* out = (float*)d_out;

    llsa_fused_kernel<<<NBLK, TPB>>>(series, weight, bias, thr, out);
}

// round 17
// speedup vs baseline: 2.1882x; 1.0037x over previous
#include <cuda_runtime.h>

// Problem constants (fixed by the reference)
#define BB   256
#define TT   16384
#define WIN  5
#define HID  5
#define NN   (TT - WIN)   // 16379

// ---- Fused kernel config ----
#define TPB    512                          // 16 warps, 1 CTA/SM (128-reg budget)
#define NWARP  16
#define RPW    16                           // rows per warp (16*16 = 256 = BB)
#define NPB    120                          // n per block
#define NBLK   ((NN + NPB - 1) / NPB)       // 137 blocks (one wave)
#define TCOV   128                          // stat positions covered per warp
#define ROWB   132                          // stat row stride (128 + 4 pad, 16B-aligned)
#define NPOOL  8
#define NSTAT  7                            // C_0..C_5, mean
#define STATF  (NSTAT * ROWB)               // 924 floats
#define PF     8                            // register prefetch depth (rows)

__device__ __forceinline__ int triidx(int i, int j) {
    return 7 * i - (i * (i - 1)) / 2 + (j - i);   // upper-tri 7x7, i <= j
}

__global__ void __launch_bounds__(TPB, 1)
llsa_fused_kernel(const float* __restrict__ series,
                  const float* __restrict__ weight,
                  const float* __restrict__ bias,
                  const float* __restrict__ thr_p,
                  float* __restrict__ out)
{
    __shared__ float pool[NPOOL * STATF];    // 29.6 KB
    __shared__ float R[NSTAT][ROWB];
    __shared__ float sM[28];
    __shared__ float sloss[NPB + 2];

    const int tid  = threadIdx.x;
    const int slot = tid & 31;        // lane: owns stats k = slot*4 .. +3
    const int rg   = tid >> 5;        // warp id -> rows rg*16 .. rg*16+15
    const int n0   = blockIdx.x * NPB;
    const int tl   = slot * 4;

    // Disjoint per-lane float4 column; clamp keeps last block in-bounds
    // (clamped lanes' stats are never consumed downstream).
    int tcol = n0 + tl;
    if (tcol > TT - 4) tcol = TT - 4;
    const float* src = series + (size_t)(rg * RPW) * TT + tcol;

    // ---- Deep register prefetch pipeline: 8 rows in flight ----
    float4 buf[PF];
#pragma unroll
    for (int r = 0; r < PF; r++)
        buf[r] = __ldg(reinterpret_cast<const float4*>(src + (size_t)r * TT));

    float acc[NSTAT][4];
#pragma unroll
    for (int s = 0; s < NSTAT; s++)
#pragma unroll
        for (int i = 0; i < 4; i++) acc[s][i] = 0.0f;

#pragma unroll
    for (int r = 0; r < RPW; r++) {
        const float4 v0 = buf[r & (PF - 1)];
        if (r + PF < RPW)
            buf[r & (PF - 1)] = __ldg(reinterpret_cast<const float4*>(
                                          src + (size_t)(r + PF) * TT));

        // Halo from neighbor lanes (edge-lane garbage is never consumed).
        const float x4 = __shfl_down_sync(0xffffffffu, v0.x, 1);
        const float x5 = __shfl_down_sync(0xffffffffu, v0.y, 1);
        const float x6 = __shfl_down_sync(0xffffffffu, v0.z, 1);
        const float x7 = __shfl_down_sync(0xffffffffu, v0.w, 1);
        const float x8 = __shfl_down_sync(0xffffffffu, v0.x, 2);
        const float x9 = __shfl_down_sync(0xffffffffu, v0.y, 2);
        const float x[10] = {v0.x, v0.y, v0.z, v0.w, x4, x5, x6, x7, x8, x9};

#pragma unroll
        for (int i = 0; i < 4; i++) {
            acc[6][i] += x[i];
#pragma unroll
            for (int d = 0; d < 6; d++)
                acc[d][i] = fmaf(x[i], x[i + d], acc[d][i]);
        }
    }

    // ---- Two-stage cross-warp reduction (16 warps -> 8 pool slots -> R) ----
    if (rg >= NPOOL) {
#pragma unroll
        for (int s = 0; s < NSTAT; s++) {
            float4 v = make_float4(acc[s][0], acc[s][1], acc[s][2], acc[s][3]);
            *reinterpret_cast<float4*>(
                &pool[(rg - NPOOL) * STATF + s * ROWB + tl]) = v;
        }
    }
    __syncthreads();
    if (rg < NPOOL) {
#pragma unroll
        for (int s = 0; s < NSTAT; s++) {
            float* p = &pool[rg * STATF + s * ROWB + tl];
            float4 v = *reinterpret_cast<const float4*>(p);
            v.x += acc[s][0]; v.y += acc[s][1];
            v.z += acc[s][2]; v.w += acc[s][3];
            *reinterpret_cast<float4*>(p) = v;
        }
    }
    __syncthreads();

    for (int e = tid; e < NSTAT * TCOV; e += TPB) {   // 896 entries, 2 iters
        const int s = e >> 7;
        const int k = e & 127;
        float v = 0.0f;
#pragma unroll
        for (int w = 0; w < NPOOL; w++)
            v += pool[w * STATF + s * ROWB + k];
        R[s][k] = v;
    }

    // ---- Build folded M: r_h = (W[h,0..4], 0, b_h), r_h[1+h] -= 1 ----
    if (tid < 28) {
        int i = 0, j = tid;
        while (j >= 7 - i) { j -= 7 - i; i++; }
        j += i;
        float m = 0.0f;
#pragma unroll
        for (int h = 0; h < HID; h++) {
            float ri = (i < WIN) ? __ldg(&weight[h * WIN + i]) : 0.0f;
            float rj = (j < WIN) ? __ldg(&weight[h * WIN + j]) : 0.0f;
            if (i == 1 + h) ri -= 1.0f;
            if (j == 1 + h) rj -= 1.0f;
            if (i == 6) ri = __ldg(&bias[h]);
            if (j == 6) rj = __ldg(&bias[h]);
            m = fmaf(ri, rj, m);
        }
        sM[tid] = (i == j) ? m : 2.0f * m;
    }
    __syncthreads();

    // ---- loss[n0+k] = (1/(B*H)) * sum_{i<=j} Mfold_ij * Z_ij ----
    auto compute_loss = [&](int k) -> float {
        float s = sM[triidx(6, 6)] * (float)BB;
#pragma unroll
        for (int i = 0; i < 6; i++)
            s = fmaf(sM[triidx(i, 6)], R[6][k + i], s);   // mean terms
#pragma unroll
        for (int i = 0; i < 6; i++)
            s = fmaf(sM[triidx(i, i)], R[0][k + i], s);   // diagonal (lag 0)
#pragma unroll
        for (int i = 0; i < 6; i++)
#pragma unroll
            for (int j = i + 1; j < 6; j++)
                s = fmaf(sM[triidx(i, j)], R[j - i][k + i], s);
        return s * (1.0f / (float)(BB * HID));
    };

    // NPB losses + one neighbor (k = NPB) for the cross-block diff.
    float L = 0.0f;
    const int n = n0 + tid;
    if (tid <= NPB && n < NN) L = compute_loss(tid);
    if (tid <= NPB) sloss[tid] = L;
    __syncthreads();

    if (tid < NPB && n < NN) {
        out[n] = L;
        if (n < NN - 1) {
            const float d = fabsf(sloss[tid + 1] - L);
            out[NN + n] = d;
            out[2 * NN - 1 + n] = (d > __ldg(thr_p)) ? 1.0f : 0.0f;
        }
    }
}

extern "C" void kernel_launch(void* const* d_in, const int* in_sizes, int n_in,
                              void* d_out, int out_size)
{
    const float* series = (const float*)d_in[0];
    const float* weight = (const float*)d_in[1];
    const float* bias   = (const float*)d_in[2];
    const float* thr    = (const float*)d_in[3];
    float* out = (float*)d_out;

    llsa_fused_kernel<<<NBLK, TPB>>>(series, weight, bias, thr, out);
}